// round 11
// baseline (speedup 1.0000x reference)
#include <cuda_runtime.h>
#include <cuda_fp16.h>
#include <math.h>

#define BATCH 4
#define TQL   128
#define TKL   512
#define ND    512
#define OD    512
#define MROWS (BATCH * TQL)   // 512

// Scratch (device globals -- no allocation allowed)
__device__ __align__(16) float g_attq  [MROWS * ND];
__device__ __align__(16) float g_ctx   [MROWS * ND];
__device__ __align__(16) float g_scores[MROWS * TKL];
__device__ __align__(16) float g_part  [8 * MROWS * 512];   // split-K partials

__device__ __forceinline__ __half2 tanh2_h2(__half2 x) {
    unsigned int u = *reinterpret_cast<unsigned int*>(&x);
    asm("tanh.approx.f16x2 %0, %0;" : "+r"(u));
    return *reinterpret_cast<__half2*>(&u);
}

// ----------------------------------------------------------------------------
// Split-K NT GEMM (A,B row-major, K contiguous):
//   part[z][m][n] = sum_{k in chunk z} A[m,k] * B[n,k]
// 64x64 tile, BK=16, 256 threads, 4x4 micro-tile, double-buffered smem.
// ----------------------------------------------------------------------------
template <int K, int SPLITS, bool SECOND_IS_CTX>
__global__ __launch_bounds__(256, 3) void gemm_nt_splitk(
    const float* __restrict__ A0,
    const float* __restrict__ B)
{
    constexpr int CHUNK  = K / SPLITS;
    constexpr int STAGES = CHUNK / 16;

    __shared__ float As[2][16][68];
    __shared__ float Bs[2][16][68];

    const int tid = threadIdx.x;
    const int r   = tid >> 2;
    const int c   = tid & 3;
    const int ty  = tid >> 4;
    const int tx  = tid & 15;
    const int m0  = blockIdx.y * 64;
    const int n0  = blockIdx.x * 64;
    const int kst = blockIdx.z * CHUNK;

    float acc[4][4] = {};

    auto a_addr = [&](int kb) -> const float* {
        if (SECOND_IS_CTX && kb >= ND)
            return g_ctx + (size_t)(m0 + r) * ND + (kb - ND) + 4 * c;
        return A0 + (size_t)(m0 + r) * ND + kb + 4 * c;
    };

    float4 av = *(const float4*)a_addr(kst);
    float4 bv = *(const float4*)(B + (size_t)(n0 + r) * K + kst + 4 * c);
    {
        float a4[4] = {av.x, av.y, av.z, av.w};
        float b4[4] = {bv.x, bv.y, bv.z, bv.w};
#pragma unroll
        for (int j = 0; j < 4; j++) {
            As[0][4 * c + j][r] = a4[j];
            Bs[0][4 * c + j][r] = b4[j];
        }
    }
    __syncthreads();

    int buf = 0;
#pragma unroll 1
    for (int s = 0; s < STAGES; s++) {
        float4 anx, bnx;
        if (s + 1 < STAGES) {
            const int kb = kst + (s + 1) * 16;
            anx = *(const float4*)a_addr(kb);
            bnx = *(const float4*)(B + (size_t)(n0 + r) * K + kb + 4 * c);
        }

#pragma unroll
        for (int kk = 0; kk < 16; kk++) {
            float4 a = *(const float4*)&As[buf][kk][ty * 4];
            float4 b = *(const float4*)&Bs[buf][kk][tx * 4];
            float a4[4] = {a.x, a.y, a.z, a.w};
            float b4[4] = {b.x, b.y, b.z, b.w};
#pragma unroll
            for (int i = 0; i < 4; i++)
#pragma unroll
                for (int j = 0; j < 4; j++)
                    acc[i][j] += a4[i] * b4[j];
        }

        if (s + 1 < STAGES) {
            const int nb = buf ^ 1;
            float a4[4] = {anx.x, anx.y, anx.z, anx.w};
            float b4[4] = {bnx.x, bnx.y, bnx.z, bnx.w};
#pragma unroll
            for (int j = 0; j < 4; j++) {
                As[nb][4 * c + j][r] = a4[j];
                Bs[nb][4 * c + j][r] = b4[j];
            }
            __syncthreads();
            buf = nb;
        }
    }

    float* pp = g_part + (size_t)blockIdx.z * MROWS * 512;
#pragma unroll
    for (int i = 0; i < 4; i++) {
        float4 v = make_float4(acc[i][0], acc[i][1], acc[i][2], acc[i][3]);
        *(float4*)&pp[(size_t)(m0 + ty * 4 + i) * 512 + n0 + tx * 4] = v;
    }
}

// ----------------------------------------------------------------------------
// Split-K NN GEMM for context: part[z][m][n] = sum_k P[m,k] * V_b[k,n]
// ----------------------------------------------------------------------------
template <int SPLITS>
__global__ __launch_bounds__(256, 3) void gemm_ctx_splitk(
    const float* __restrict__ P,
    const float* __restrict__ values)
{
    constexpr int CHUNK  = TKL / SPLITS;
    constexpr int STAGES = CHUNK / 16;

    __shared__ float As[2][16][68];
    __shared__ float Bs[2][16][68];

    const int tid = threadIdx.x;
    const int r   = tid >> 2;
    const int c   = tid & 3;
    const int bk  = tid >> 4;
    const int bn  = (tid & 15) * 4;
    const int ty  = tid >> 4;
    const int tx  = tid & 15;
    const int m0  = blockIdx.y * 64;
    const int n0  = blockIdx.x * 64;
    const int kst = blockIdx.z * CHUNK;

    const float* valb = values + (size_t)(m0 >> 7) * TKL * ND;

    float acc[4][4] = {};

    {
        float4 av = *(const float4*)(P + (size_t)(m0 + r) * TKL + kst + 4 * c);
        float4 bvv = *(const float4*)(valb + (size_t)(kst + bk) * ND + n0 + bn);
        float a4[4] = {av.x, av.y, av.z, av.w};
#pragma unroll
        for (int j = 0; j < 4; j++) As[0][4 * c + j][r] = a4[j];
        *(float4*)&Bs[0][bk][bn] = bvv;
    }
    __syncthreads();

    int buf = 0;
#pragma unroll 1
    for (int s = 0; s < STAGES; s++) {
        float4 anx, bnx;
        if (s + 1 < STAGES) {
            const int kb = kst + (s + 1) * 16;
            anx = *(const float4*)(P + (size_t)(m0 + r) * TKL + kb + 4 * c);
            bnx = *(const float4*)(valb + (size_t)(kb + bk) * ND + n0 + bn);
        }

#pragma unroll
        for (int kk = 0; kk < 16; kk++) {
            float4 a = *(const float4*)&As[buf][kk][ty * 4];
            float4 b = *(const float4*)&Bs[buf][kk][tx * 4];
            float a4[4] = {a.x, a.y, a.z, a.w};
            float b4[4] = {b.x, b.y, b.z, b.w};
#pragma unroll
            for (int i = 0; i < 4; i++)
#pragma unroll
                for (int j = 0; j < 4; j++)
                    acc[i][j] += a4[i] * b4[j];
        }

        if (s + 1 < STAGES) {
            const int nb = buf ^ 1;
            float a4[4] = {anx.x, anx.y, anx.z, anx.w};
#pragma unroll
            for (int j = 0; j < 4; j++) As[nb][4 * c + j][r] = a4[j];
            *(float4*)&Bs[nb][bk][bn] = bnx;
            __syncthreads();
            buf = nb;
        }
    }

    float* pp = g_part + (size_t)blockIdx.z * MROWS * 512;
#pragma unroll
    for (int i = 0; i < 4; i++) {
        float4 v = make_float4(acc[i][0], acc[i][1], acc[i][2], acc[i][3]);
        *(float4*)&pp[(size_t)(m0 + ty * 4 + i) * 512 + n0 + tx * 4] = v;
    }
}

// ----------------------------------------------------------------------------
// Split-K reduction. MODE: 0 = +bias -> g_attq; 1 = +bias, tanh -> dext;
//                          2 = no bias -> g_ctx
// ----------------------------------------------------------------------------
template <int SPLITS, int MODE>
__global__ __launch_bounds__(256) void reduce_part(
    const float* __restrict__ bias,
    float* __restrict__ dext)
{
    float* dst = (MODE == 0) ? g_attq : (MODE == 2) ? g_ctx : dext;
    const int idx = blockIdx.x * 256 + threadIdx.x;
    const float4* p = (const float4*)g_part;

    float4 s = p[idx];
#pragma unroll
    for (int sp = 1; sp < SPLITS; sp++) {
        float4 t = p[(size_t)sp * (MROWS * 512 / 4) + idx];
        s.x += t.x; s.y += t.y; s.z += t.z; s.w += t.w;
    }
    if (MODE != 2) {
        const float4 bb = ((const float4*)bias)[idx & (512 / 4 - 1)];
        s.x += bb.x; s.y += bb.y; s.z += bb.z; s.w += bb.w;
    }
    if (MODE == 1) {
        s.x = tanhf(s.x); s.y = tanhf(s.y); s.z = tanhf(s.z); s.w = tanhf(s.w);
    }
    ((float4*)dst)[idx] = s;
}

// ----------------------------------------------------------------------------
// Scores kernel: grid 256 = khalf(2) x qgroup(32) x b(4); 256 threads.
// Full f16x2 inner loop: HADD2 + tanh.approx.f16x2 + HFMA2 (3 ops / 2 elems).
// f16x2 accumulator holds only 8 terms, flushed to f32 once per key per q.
// ----------------------------------------------------------------------------
__global__ __launch_bounds__(256) void attn_scores(
    const float* __restrict__ keys,
    const float* __restrict__ w_att,
    const float* __restrict__ b_att)
{
    const int tid  = threadIdx.x;
    const int wid  = tid >> 5;
    const int lane = tid & 31;
    const int kh   = blockIdx.x & 1;
    const int q0   = ((blockIdx.x >> 1) & 31) << 2;
    const int b    = blockIdx.x >> 6;

    // Pre-convert w_att and 4 att_query rows to half2 (lane owns 16 n-positions)
    __half2 w2[8];
    __half2 a2[4][8];
#pragma unroll
    for (int i = 0; i < 4; i++) {
        float4 w4 = *(const float4*)(w_att + i * 128 + lane * 4);
        w2[i * 2 + 0] = __floats2half2_rn(w4.x, w4.y);
        w2[i * 2 + 1] = __floats2half2_rn(w4.z, w4.w);
#pragma unroll
        for (int q = 0; q < 4; q++) {
            float4 a4 = *(const float4*)(g_attq + (size_t)(b * TQL + q0 + q) * ND + i * 128 + lane * 4);
            a2[q][i * 2 + 0] = __floats2half2_rn(a4.x, a4.y);
            a2[q][i * 2 + 1] = __floats2half2_rn(a4.z, a4.w);
        }
    }
    const float batt = b_att[0];
    const float* keyb = keys + (size_t)b * TKL * ND;
    float* sco = g_scores + (size_t)(b * TQL + q0) * TKL;

    const int kend = kh * 256 + 256;
    for (int k = kh * 256 + wid; k < kend; k += 8) {
        const float* kr = keyb + (size_t)k * ND;

        // Load + pack key values once (shared across the 4 queries)
        __half2 kv2[8];
#pragma unroll
        for (int i = 0; i < 4; i++) {
            float4 k4 = *(const float4*)(kr + i * 128 + lane * 4);
            kv2[i * 2 + 0] = __floats2half2_rn(k4.x, k4.y);
            kv2[i * 2 + 1] = __floats2half2_rn(k4.z, k4.w);
        }

        float acc[4];
#pragma unroll
        for (int q = 0; q < 4; q++) {
            __half2 acc2 = __floats2half2_rn(0.f, 0.f);
#pragma unroll
            for (int p = 0; p < 8; p++) {
                __half2 t = tanh2_h2(__hadd2(a2[q][p], kv2[p]));
                acc2 = __hfma2(w2[p], t, acc2);
            }
            float2 f = __half22float2(acc2);
            acc[q] = f.x + f.y;
        }

#pragma unroll
        for (int off = 16; off; off >>= 1) {
#pragma unroll
            for (int q = 0; q < 4; q++)
                acc[q] += __shfl_xor_sync(0xffffffffu, acc[q], off);
        }
        if (lane == 0) {
#pragma unroll
            for (int q = 0; q < 4; q++)
                sco[q * TKL + k] = acc[q] + batt;
        }
    }
}

// ----------------------------------------------------------------------------
// Row softmax: one warp per row, register-resident. Grid 128 x 128 threads.
// ----------------------------------------------------------------------------
__global__ __launch_bounds__(128) void softmax_rows(float* __restrict__ probs)
{
    const int wid  = threadIdx.x >> 5;
    const int lane = threadIdx.x & 31;
    const int row  = blockIdx.x * 4 + wid;

    const float* src = g_scores + (size_t)row * TKL;
    float v[16];
    float m = -1e30f;
#pragma unroll
    for (int i = 0; i < 4; i++) {
        float4 t = *(const float4*)(src + i * 128 + lane * 4);
        v[i * 4 + 0] = t.x; v[i * 4 + 1] = t.y; v[i * 4 + 2] = t.z; v[i * 4 + 3] = t.w;
        m = fmaxf(m, fmaxf(fmaxf(t.x, t.y), fmaxf(t.z, t.w)));
    }
#pragma unroll
    for (int off = 16; off; off >>= 1) m = fmaxf(m, __shfl_xor_sync(0xffffffffu, m, off));
    float s = 0.f;
#pragma unroll
    for (int i = 0; i < 16; i++) {
        v[i] = __expf(v[i] - m);
        s += v[i];
    }
#pragma unroll
    for (int off = 16; off; off >>= 1) s += __shfl_xor_sync(0xffffffffu, s, off);
    const float inv = 1.0f / s;
    float* dst = probs + (size_t)row * TKL;
#pragma unroll
    for (int i = 0; i < 4; i++) {
        float4 t = make_float4(v[i * 4 + 0] * inv, v[i * 4 + 1] * inv,
                               v[i * 4 + 2] * inv, v[i * 4 + 3] * inv);
        *(float4*)(dst + i * 128 + lane * 4) = t;
    }
}

// ----------------------------------------------------------------------------
// Launch sequence (graph-capturable, allocation-free)
// ----------------------------------------------------------------------------
extern "C" void kernel_launch(void* const* d_in, const int* in_sizes, int n_in,
                              void* d_out, int out_size)
{
    const float* query  = (const float*)d_in[0];
    const float* keys   = (const float*)d_in[1];
    const float* values = (const float*)d_in[2];
    const float* W_q    = (const float*)d_in[3];
    const float* b_q    = (const float*)d_in[4];
    const float* w_att  = (const float*)d_in[5];
    const float* b_att  = (const float*)d_in[6];
    const float* W_out  = (const float*)d_in[7];
    const float* b_out  = (const float*)d_in[8];

    float* out   = (float*)d_out;
    float* probs = out + (size_t)MROWS * OD;

    // 1) att_query = query @ W_q^T + b_q
    gemm_nt_splitk<ND, 8, false><<<dim3(8, 8, 8), 256>>>(query, W_q);
    reduce_part<8, 0><<<256, 256>>>(b_q, nullptr);

    // 2) scores -> softmax -> probs (written directly to output)
    attn_scores<<<256, 256>>>(keys, w_att, b_att);
    softmax_rows<<<128, 128>>>(probs);

    // 3) context = probs @ values (per-batch NN GEMM, split-K)
    gemm_ctx_splitk<8><<<dim3(8, 8, 8), 256>>>(probs, values);
    reduce_part<8, 2><<<256, 256>>>(nullptr, nullptr);

    // 4) out = tanh([query|ctx] @ W_out^T + b_out)
    gemm_nt_splitk<2 * ND, 8, true><<<dim3(8, 8, 8), 256>>>(query, W_out);
    reduce_part<8, 1><<<256, 256>>>(b_out, out);
}

// round 12
// speedup vs baseline: 1.1247x; 1.1247x over previous
#include <cuda_runtime.h>
#include <math.h>

#define BATCH 4
#define TQL   128
#define TKL   512
#define ND    512
#define OD    512
#define MROWS (BATCH * TQL)     // 512
#define SLAB  (MROWS * 512)     // one partial slab

// Scratch (device globals -- no allocation allowed)
__device__ __align__(16) float g_ctx   [MROWS * ND];
__device__ __align__(16) float g_scores[MROWS * TKL];
__device__ __align__(16) float g_part  [8 * SLAB];   // gemm1 partials, then ctx partials
__device__ __align__(16) float g_part2 [8 * SLAB];   // out-GEMM partials (qhalf 0-3, chalf 4-7)

__device__ __forceinline__ float fast_tanh(float x) {
    float y;
    asm("tanh.approx.f32 %0, %1;" : "=f"(y) : "f"(x));
    return y;
}

// ----------------------------------------------------------------------------
// Split-K NT GEMM body over a K=512 range:
//   part[z0+bz][m][n] = sum_{k in chunk bz} A0[m,k] * B[n, boff+k]
// A0: [512 x 512] row-major (stride 512). B row stride = bstride.
// 64x64 tile, BK=16, 256 threads, 4x4 micro-tile, double-buffered smem.
// ----------------------------------------------------------------------------
template <int SPLITS>
__device__ __forceinline__ void gemm_body(
    const float* __restrict__ A0, const float* __restrict__ B,
    int bstride, int boff, float* __restrict__ part, int z0,
    int bx, int by, int bz)
{
    constexpr int CHUNK  = 512 / SPLITS;
    constexpr int STAGES = CHUNK / 16;

    __shared__ float As[2][16][68];
    __shared__ float Bs[2][16][68];

    const int tid = threadIdx.x;
    const int r   = tid >> 2;
    const int c   = tid & 3;
    const int ty  = tid >> 4;
    const int tx  = tid & 15;
    const int m0  = by * 64;
    const int n0  = bx * 64;
    const int kst = bz * CHUNK;

    float acc[4][4] = {};

    // prologue: stage 0
    {
        float4 av = *(const float4*)(A0 + (size_t)(m0 + r) * 512 + kst + 4 * c);
        float4 bv = *(const float4*)(B + (size_t)(n0 + r) * bstride + boff + kst + 4 * c);
        float a4[4] = {av.x, av.y, av.z, av.w};
        float b4[4] = {bv.x, bv.y, bv.z, bv.w};
#pragma unroll
        for (int j = 0; j < 4; j++) {
            As[0][4 * c + j][r] = a4[j];
            Bs[0][4 * c + j][r] = b4[j];
        }
    }
    __syncthreads();

    int buf = 0;
#pragma unroll 1
    for (int s = 0; s < STAGES; s++) {
        float4 anx, bnx;
        if (s + 1 < STAGES) {
            const int kb = kst + (s + 1) * 16;
            anx = *(const float4*)(A0 + (size_t)(m0 + r) * 512 + kb + 4 * c);
            bnx = *(const float4*)(B + (size_t)(n0 + r) * bstride + boff + kb + 4 * c);
        }

#pragma unroll
        for (int kk = 0; kk < 16; kk++) {
            float4 a = *(const float4*)&As[buf][kk][ty * 4];
            float4 b = *(const float4*)&Bs[buf][kk][tx * 4];
            float a4[4] = {a.x, a.y, a.z, a.w};
            float b4[4] = {b.x, b.y, b.z, b.w};
#pragma unroll
            for (int i = 0; i < 4; i++)
#pragma unroll
                for (int j = 0; j < 4; j++)
                    acc[i][j] += a4[i] * b4[j];
        }

        if (s + 1 < STAGES) {
            const int nb = buf ^ 1;
            float a4[4] = {anx.x, anx.y, anx.z, anx.w};
            float b4[4] = {bnx.x, bnx.y, bnx.z, bnx.w};
#pragma unroll
            for (int j = 0; j < 4; j++) {
                As[nb][4 * c + j][r] = a4[j];
                Bs[nb][4 * c + j][r] = b4[j];
            }
            __syncthreads();
            buf = nb;
        }
    }

    float* pp = part + (size_t)(z0 + bz) * SLAB;
#pragma unroll
    for (int i = 0; i < 4; i++) {
        float4 v = make_float4(acc[i][0], acc[i][1], acc[i][2], acc[i][3]);
        *(float4*)&pp[(size_t)(m0 + ty * 4 + i) * 512 + n0 + tx * 4] = v;
    }
}

// ----------------------------------------------------------------------------
// Scores body (f32 MUFU tanh) with FUSED split-K reduce of att_query:
// block builds its 4 att_query rows in smem from g_part (8 slabs) + b_q,
// then computes scores for 4 queries x 256 keys (kh half).
// ----------------------------------------------------------------------------
__device__ __forceinline__ void scores_body(
    const float* __restrict__ keys,
    const float* __restrict__ w_att,
    const float* __restrict__ b_att,
    const float* __restrict__ b_q,
    int bi)
{
    __shared__ float s_aq[4][512];   // 8 KB

    const int tid  = threadIdx.x;
    const int wid  = tid >> 5;
    const int lane = tid & 31;
    const int kh   = bi & 1;
    const int q0   = ((bi >> 1) & 31) << 2;
    const int b    = bi >> 6;

    // Cooperative reduce: att_query rows = sum of 8 partial slabs + b_q
    for (int idx = tid; idx < 4 * 512; idx += 256) {
        const int q = idx >> 9, n = idx & 511;
        const size_t row = (size_t)(b * TQL + q0 + q) * 512 + n;
        float s = b_q[n];
#pragma unroll
        for (int sp = 0; sp < 8; sp++) s += g_part[(size_t)sp * SLAB + row];
        s_aq[q][n] = s;
    }
    __syncthreads();

    // Register-resident w_att and att_query (lane owns 16 n-positions)
    float wreg[16];
    float areg[4][16];
#pragma unroll
    for (int i = 0; i < 4; i++) {
        float4 w4 = *(const float4*)(w_att + i * 128 + lane * 4);
        wreg[i * 4 + 0] = w4.x; wreg[i * 4 + 1] = w4.y;
        wreg[i * 4 + 2] = w4.z; wreg[i * 4 + 3] = w4.w;
#pragma unroll
        for (int q = 0; q < 4; q++) {
            float4 a4 = *(const float4*)&s_aq[q][i * 128 + lane * 4];
            areg[q][i * 4 + 0] = a4.x; areg[q][i * 4 + 1] = a4.y;
            areg[q][i * 4 + 2] = a4.z; areg[q][i * 4 + 3] = a4.w;
        }
    }
    const float batt = b_att[0];
    const float* keyb = keys + (size_t)b * TKL * ND;
    float* sco = g_scores + (size_t)(b * TQL + q0) * TKL;

    const int kend = kh * 256 + 256;
    for (int k = kh * 256 + wid; k < kend; k += 8) {
        const float* kr = keyb + (size_t)k * ND;
        float acc0 = 0.f, acc1 = 0.f, acc2 = 0.f, acc3 = 0.f;
#pragma unroll
        for (int i = 0; i < 4; i++) {
            float4 k4 = *(const float4*)(kr + i * 128 + lane * 4);
            float kv[4] = {k4.x, k4.y, k4.z, k4.w};
#pragma unroll
            for (int j = 0; j < 4; j++) {
                const float w = wreg[i * 4 + j];
                acc0 += w * fast_tanh(areg[0][i * 4 + j] + kv[j]);
                acc1 += w * fast_tanh(areg[1][i * 4 + j] + kv[j]);
                acc2 += w * fast_tanh(areg[2][i * 4 + j] + kv[j]);
                acc3 += w * fast_tanh(areg[3][i * 4 + j] + kv[j]);
            }
        }
#pragma unroll
        for (int off = 16; off; off >>= 1) {
            acc0 += __shfl_xor_sync(0xffffffffu, acc0, off);
            acc1 += __shfl_xor_sync(0xffffffffu, acc1, off);
            acc2 += __shfl_xor_sync(0xffffffffu, acc2, off);
            acc3 += __shfl_xor_sync(0xffffffffu, acc3, off);
        }
        if (lane == 0) {
            sco[0 * TKL + k] = acc0 + batt;
            sco[1 * TKL + k] = acc1 + batt;
            sco[2 * TKL + k] = acc2 + batt;
            sco[3 * TKL + k] = acc3 + batt;
        }
    }
}

// ----------------------------------------------------------------------------
// MEGA: blocks [0,256) = scores (MUFU-bound); blocks [256,512) = out-GEMM
// query-half (FFMA-bound). Heterogeneous roles overlap the two pipes.
// ----------------------------------------------------------------------------
__global__ __launch_bounds__(256) void mega_scores_qgemm(
    const float* __restrict__ keys,
    const float* __restrict__ w_att,
    const float* __restrict__ b_att,
    const float* __restrict__ b_q,
    const float* __restrict__ query,
    const float* __restrict__ W_out)
{
    if (blockIdx.x < 256) {
        scores_body(keys, w_att, b_att, b_q, blockIdx.x);
    } else {
        const int g = blockIdx.x - 256;      // 256 = 8n x 8m x 4z
        gemm_body<4>(query, W_out, 1024, 0, g_part2, 0,
                     g & 7, (g >> 3) & 7, g >> 6);
    }
}

// ----------------------------------------------------------------------------
// Standalone GEMM kernels
// ----------------------------------------------------------------------------
__global__ __launch_bounds__(256, 3) void gemm_attq(
    const float* __restrict__ query, const float* __restrict__ W_q)
{
    gemm_body<8>(query, W_q, 512, 0, g_part, 0, blockIdx.x, blockIdx.y, blockIdx.z);
}

__global__ __launch_bounds__(256, 3) void gemm_out_chalf(const float* __restrict__ W_out)
{
    gemm_body<4>(g_ctx, W_out, 1024, 512, g_part2, 4, blockIdx.x, blockIdx.y, blockIdx.z);
}

// ----------------------------------------------------------------------------
// Split-K NN GEMM for context: part[z][m][n] = sum_k P[m,k] * V_b[k,n]
// ----------------------------------------------------------------------------
template <int SPLITS>
__global__ __launch_bounds__(256, 3) void gemm_ctx_splitk(
    const float* __restrict__ P,
    const float* __restrict__ values)
{
    constexpr int CHUNK  = TKL / SPLITS;
    constexpr int STAGES = CHUNK / 16;

    __shared__ float As[2][16][68];
    __shared__ float Bs[2][16][68];

    const int tid = threadIdx.x;
    const int r   = tid >> 2;
    const int c   = tid & 3;
    const int bk  = tid >> 4;
    const int bn  = (tid & 15) * 4;
    const int ty  = tid >> 4;
    const int tx  = tid & 15;
    const int m0  = blockIdx.y * 64;
    const int n0  = blockIdx.x * 64;
    const int kst = blockIdx.z * CHUNK;

    const float* valb = values + (size_t)(m0 >> 7) * TKL * ND;

    float acc[4][4] = {};

    {
        float4 av = *(const float4*)(P + (size_t)(m0 + r) * TKL + kst + 4 * c);
        float4 bvv = *(const float4*)(valb + (size_t)(kst + bk) * ND + n0 + bn);
        float a4[4] = {av.x, av.y, av.z, av.w};
#pragma unroll
        for (int j = 0; j < 4; j++) As[0][4 * c + j][r] = a4[j];
        *(float4*)&Bs[0][bk][bn] = bvv;
    }
    __syncthreads();

    int buf = 0;
#pragma unroll 1
    for (int s = 0; s < STAGES; s++) {
        float4 anx, bnx;
        if (s + 1 < STAGES) {
            const int kb = kst + (s + 1) * 16;
            anx = *(const float4*)(P + (size_t)(m0 + r) * TKL + kb + 4 * c);
            bnx = *(const float4*)(valb + (size_t)(kb + bk) * ND + n0 + bn);
        }

#pragma unroll
        for (int kk = 0; kk < 16; kk++) {
            float4 a = *(const float4*)&As[buf][kk][ty * 4];
            float4 b = *(const float4*)&Bs[buf][kk][tx * 4];
            float a4[4] = {a.x, a.y, a.z, a.w};
            float b4[4] = {b.x, b.y, b.z, b.w};
#pragma unroll
            for (int i = 0; i < 4; i++)
#pragma unroll
                for (int j = 0; j < 4; j++)
                    acc[i][j] += a4[i] * b4[j];
        }

        if (s + 1 < STAGES) {
            const int nb = buf ^ 1;
            float a4[4] = {anx.x, anx.y, anx.z, anx.w};
#pragma unroll
            for (int j = 0; j < 4; j++) As[nb][4 * c + j][r] = a4[j];
            *(float4*)&Bs[nb][bk][bn] = bnx;
            __syncthreads();
            buf = nb;
        }
    }

    float* pp = g_part + (size_t)blockIdx.z * SLAB;
#pragma unroll
    for (int i = 0; i < 4; i++) {
        float4 v = make_float4(acc[i][0], acc[i][1], acc[i][2], acc[i][3]);
        *(float4*)&pp[(size_t)(m0 + ty * 4 + i) * 512 + n0 + tx * 4] = v;
    }
}

// ----------------------------------------------------------------------------
// Reductions. reduce_ctx: sum 8 slabs of g_part -> g_ctx.
//             reduce_out: sum 8 slabs of g_part2 + b_out, tanh -> out.
// ----------------------------------------------------------------------------
__global__ __launch_bounds__(256) void reduce_ctx_k()
{
    const int idx = blockIdx.x * 256 + threadIdx.x;
    const float4* p = (const float4*)g_part;
    float4 s = p[idx];
#pragma unroll
    for (int sp = 1; sp < 8; sp++) {
        float4 t = p[(size_t)sp * (SLAB / 4) + idx];
        s.x += t.x; s.y += t.y; s.z += t.z; s.w += t.w;
    }
    ((float4*)g_ctx)[idx] = s;
}

__global__ __launch_bounds__(256) void reduce_out_k(
    const float* __restrict__ bias, float* __restrict__ dext)
{
    const int idx = blockIdx.x * 256 + threadIdx.x;
    const float4* p = (const float4*)g_part2;
    float4 s = p[idx];
#pragma unroll
    for (int sp = 1; sp < 8; sp++) {
        float4 t = p[(size_t)sp * (SLAB / 4) + idx];
        s.x += t.x; s.y += t.y; s.z += t.z; s.w += t.w;
    }
    const float4 bb = ((const float4*)bias)[idx & (512 / 4 - 1)];
    s.x = tanhf(s.x + bb.x); s.y = tanhf(s.y + bb.y);
    s.z = tanhf(s.z + bb.z); s.w = tanhf(s.w + bb.w);
    ((float4*)dext)[idx] = s;
}

// ----------------------------------------------------------------------------
// Row softmax: one warp per row, register-resident. Grid 64 x 256 threads.
// ----------------------------------------------------------------------------
__global__ __launch_bounds__(256) void softmax_rows(float* __restrict__ probs)
{
    const int wid  = threadIdx.x >> 5;
    const int lane = threadIdx.x & 31;
    const int row  = blockIdx.x * 8 + wid;

    const float* src = g_scores + (size_t)row * TKL;
    float v[16];
    float m = -1e30f;
#pragma unroll
    for (int i = 0; i < 4; i++) {
        float4 t = *(const float4*)(src + i * 128 + lane * 4);
        v[i * 4 + 0] = t.x; v[i * 4 + 1] = t.y; v[i * 4 + 2] = t.z; v[i * 4 + 3] = t.w;
        m = fmaxf(m, fmaxf(fmaxf(t.x, t.y), fmaxf(t.z, t.w)));
    }
#pragma unroll
    for (int off = 16; off; off >>= 1) m = fmaxf(m, __shfl_xor_sync(0xffffffffu, m, off));
    float s = 0.f;
#pragma unroll
    for (int i = 0; i < 16; i++) {
        v[i] = __expf(v[i] - m);
        s += v[i];
    }
#pragma unroll
    for (int off = 16; off; off >>= 1) s += __shfl_xor_sync(0xffffffffu, s, off);
    const float inv = 1.0f / s;
    float* dst = probs + (size_t)row * TKL;
#pragma unroll
    for (int i = 0; i < 4; i++) {
        float4 t = make_float4(v[i * 4 + 0] * inv, v[i * 4 + 1] * inv,
                               v[i * 4 + 2] * inv, v[i * 4 + 3] * inv);
        *(float4*)(dst + i * 128 + lane * 4) = t;
    }
}

// ----------------------------------------------------------------------------
// Launch sequence (graph-capturable, allocation-free):
//   1) gemm_attq:  query @ W_q^T partials          -> g_part[0..7]
//   2) MEGA:       scores (fused attq reduce+b_q)  -> g_scores
//                  || out-GEMM query-half          -> g_part2[0..3]
//   3) softmax                                      -> probs (output)
//   4) gemm_ctx:   probs @ values partials          -> g_part[0..7]
//   5) reduce_ctx                                   -> g_ctx
//   6) out-GEMM ctx-half                            -> g_part2[4..7]
//   7) reduce_out: sum + b_out + tanh               -> out (output)
// ----------------------------------------------------------------------------
extern "C" void kernel_launch(void* const* d_in, const int* in_sizes, int n_in,
                              void* d_out, int out_size)
{
    const float* query  = (const float*)d_in[0];
    const float* keys   = (const float*)d_in[1];
    const float* values = (const float*)d_in[2];
    const float* W_q    = (const float*)d_in[3];
    const float* b_q    = (const float*)d_in[4];
    const float* w_att  = (const float*)d_in[5];
    const float* b_att  = (const float*)d_in[6];
    const float* W_out  = (const float*)d_in[7];
    const float* b_out  = (const float*)d_in[8];

    float* out   = (float*)d_out;
    float* probs = out + (size_t)MROWS * OD;

    gemm_attq<<<dim3(8, 8, 8), 256>>>(query, W_q);

    mega_scores_qgemm<<<512, 256>>>(keys, w_att, b_att, b_q, query, W_out);

    softmax_rows<<<64, 256>>>(probs);

    gemm_ctx_splitk<8><<<dim3(8, 8, 8), 256>>>(probs, values);
    reduce_ctx_k<<<256, 256>>>();

    gemm_out_chalf<<<dim3(8, 8, 4), 256>>>(W_out);
    reduce_out_k<<<256, 256>>>(b_out, out);
}